// round 8
// baseline (speedup 1.0000x reference)
#include <cuda_runtime.h>
#include <cuda_fp16.h>
#include <math.h>

#define D    128
#define DOUT 40
#define NMAX 100000
#define EMAX 1600000

typedef unsigned long long ull;

static inline int cdiv(int a, int b) { return (a + b - 1) / b; }

// ---------------- scratch (static device globals; no allocation) ----------------
__device__ __align__(16) __half g_xw [(size_t)NMAX * D];    // fp16 gather operand
__device__ __align__(16) __half g_h  [(size_t)NMAX * D];    // fp16 hidden activations
__device__ __align__(16) __half g_xw2[(size_t)NMAX * DOUT]; // fp16 final-layer operand
__device__ float g_deg [NMAX];
__device__ float g_dinv[NMAX];
__device__ int   g_idx [2 * EMAX];
__device__ int   g_is64;
// CSR
__device__ int   g_cnt [NMAX];
__device__ int   g_rowptr[NMAX + 1];
__device__ int   g_fill[NMAX];
__device__ int   g_bsum[256];
__device__ int   g_boff[256];
__device__ int   g_esrc [EMAX];
__device__ float g_enorm[EMAX];
// BN stats, double-buffered (layer 0 -> idx 0, layer 1 -> idx 1)
__device__ __align__(16) float g_bnsum  [2 * 128];
__device__ __align__(16) float g_bnsumsq[2 * 128];

// ---------------- packed f32x2 helpers ----------------
__device__ __forceinline__ ull fma2(ull a, ull b, ull c) {
    ull d;
    asm("fma.rn.f32x2 %0, %1, %2, %3;" : "=l"(d) : "l"(a), "l"(b), "l"(c));
    return d;
}
__device__ __forceinline__ ull splat2(float x) {
    ull d;
    asm("mov.b64 %0, {%1, %1};" : "=l"(d) : "f"(x));
    return d;
}

// ---------------- index dtype detect ----------------
__global__ void detect_kernel(const unsigned* __restrict__ w, int twoE) {
    if (threadIdx.x == 0 && blockIdx.x == 0) {
        int nchk = twoE < 256 ? twoE : 256;
        int is64 = 1;
        for (int i = 0; i < nchk; i++)
            if (w[2 * i + 1] != 0u) { is64 = 0; break; }
        g_is64 = is64;
    }
}

// ---------------- convert + degree/histogram (fused) ----------------
__global__ void convert_deg_kernel(const void* __restrict__ ei,
                                   const float* __restrict__ ew, int E) {
    int i = blockIdx.x * blockDim.x + threadIdx.x;
    int twoE = 2 * E;
    if (i < twoE) {
        int v;
        if (g_is64) v = (int)((const long long*)ei)[i];
        else        v = ((const int*)ei)[i];
        g_idx[i] = v;
        if (i >= E) {
            atomicAdd(&g_deg[v], ew[i - E]);
            atomicAdd(&g_cnt[v], 1);
        }
    }
}

// ---------------- exclusive scan of g_cnt -> g_rowptr (3-pass) ----------------
__global__ void scan1(int n) {
    __shared__ int sm[512];
    int i = blockIdx.x * 512 + threadIdx.x;
    int v = (i < n) ? g_cnt[i] : 0;
    sm[threadIdx.x] = v;
    __syncthreads();
    #pragma unroll
    for (int o = 1; o < 512; o <<= 1) {
        int t = (threadIdx.x >= o) ? sm[threadIdx.x - o] : 0;
        __syncthreads();
        sm[threadIdx.x] += t;
        __syncthreads();
    }
    if (i < n) g_rowptr[i] = sm[threadIdx.x] - v;
    if (threadIdx.x == 511) g_bsum[blockIdx.x] = sm[511];
}

__global__ void scan2(int nb) {
    __shared__ int sm[256];
    int v = (threadIdx.x < nb) ? g_bsum[threadIdx.x] : 0;
    sm[threadIdx.x] = v;
    __syncthreads();
    #pragma unroll
    for (int o = 1; o < 256; o <<= 1) {
        int t = (threadIdx.x >= o) ? sm[threadIdx.x - o] : 0;
        __syncthreads();
        sm[threadIdx.x] += t;
        __syncthreads();
    }
    if (threadIdx.x < nb) g_boff[threadIdx.x] = sm[threadIdx.x] - v;
}

__global__ void scan3(int n, int E) {
    int i = blockIdx.x * blockDim.x + threadIdx.x;
    if (i < n) {
        g_rowptr[i] += g_boff[i >> 9];
        g_dinv[i] = rsqrtf(g_deg[i] + 1.0f);
    }
    if (i == 0) g_rowptr[n] = E;
}

// ---------------- CSR fill ----------------
__global__ void fill_kernel(const float* __restrict__ ew, int E) {
    int e = blockIdx.x * blockDim.x + threadIdx.x;
    if (e < E) {
        int s = g_idx[e];
        int d = g_idx[E + e];
        int pos = g_rowptr[d] + atomicAdd(&g_fill[d], 1);
        g_esrc[pos]  = s;
        g_enorm[pos] = g_dinv[s] * ew[e] * g_dinv[d];
    }
}

// ---------------- GEMM 128x128: layer 0 (fp32 in) and layer 1 (fp16 in + BN) -----
#define GEMM_SMEM ((128 * 128 + 128 * 132 + 256) * 4)

template <bool FUSE_BN>
__global__ void __launch_bounds__(256) gemm128(const float* __restrict__ Af,
                                               const __half* __restrict__ Ah,
                                               const float* __restrict__ W,
                                               __half* __restrict__ C, int n,
                                               const float* __restrict__ g,
                                               const float* __restrict__ be,
                                               int statIdx, float fn) {
    extern __shared__ float smem[];
    float* sW  = smem;                    // [128][128]
    float* sX  = smem + 128 * 128;        // [128][132] padded
    float* sSc = smem + 128 * 128 + 128 * 132;        // [128]
    float* sSh = sSc + 128;                            // [128]

    int tid = threadIdx.x;
    int row0 = blockIdx.x * 128;

    if (FUSE_BN) {
        if (tid < 128) {
            float mean = g_bnsum[statIdx * 128 + tid] / fn;
            float var  = g_bnsumsq[statIdx * 128 + tid] / fn - mean * mean;
            float sc   = g[tid] * rsqrtf(var + 1e-5f);
            sSc[tid] = sc;
            sSh[tid] = be[tid] - mean * sc;
        }
        __syncthreads();
    }

    const float4* W4  = (const float4*)W;
    float4*       sW4 = (float4*)sW;
    #pragma unroll
    for (int i = tid; i < 4096; i += 256) sW4[i] = W4[i];

    float4* sX4 = (float4*)sX;
    if (FUSE_BN) {
        const uint2* A2 = (const uint2*)(Ah + (size_t)row0 * D);
        #pragma unroll
        for (int i = tid; i < 4096; i += 256) {
            int r = i >> 5, c4 = i & 31;
            float4 v = make_float4(0.f, 0.f, 0.f, 0.f);
            if (row0 + r < n) {
                uint2 rv = A2[i];
                float2 f0 = __half22float2(*reinterpret_cast<__half2*>(&rv.x));
                float2 f1 = __half22float2(*reinterpret_cast<__half2*>(&rv.y));
                float4 sc = ((const float4*)sSc)[c4];
                float4 sh = ((const float4*)sSh)[c4];
                v.x = fmaxf(fmaf(f0.x, sc.x, sh.x), 0.f);
                v.y = fmaxf(fmaf(f0.y, sc.y, sh.y), 0.f);
                v.z = fmaxf(fmaf(f1.x, sc.z, sh.z), 0.f);
                v.w = fmaxf(fmaf(f1.y, sc.w, sh.w), 0.f);
            }
            sX4[r * 33 + c4] = v;
        }
    } else {
        const float4* A4 = (const float4*)Af + (size_t)row0 * 32;
        #pragma unroll
        for (int i = tid; i < 4096; i += 256) {
            int r = i >> 5, c4 = i & 31;
            float4 v = make_float4(0.f, 0.f, 0.f, 0.f);
            if (row0 + r < n) v = A4[i];
            sX4[r * 33 + c4] = v;
        }
    }
    __syncthreads();

    int tx = tid & 15, ty = tid >> 4;
    ull acc[8][4];
    #pragma unroll
    for (int j = 0; j < 8; j++)
        #pragma unroll
        for (int p = 0; p < 4; p++) acc[j][p] = splat2(0.f);

    const ulonglong2* sW2 = (const ulonglong2*)sW;
    #pragma unroll 2
    for (int k = 0; k < 128; k++) {
        ulonglong2 wa = sW2[k * 32 + 2 * tx];
        ulonglong2 wb = sW2[k * 32 + 2 * tx + 1];
        #pragma unroll
        for (int j = 0; j < 8; j++) {
            int row = (j < 4) ? (ty * 4 + j) : (64 + ty * 4 + (j - 4));
            ull xi = splat2(sX[row * 132 + k]);
            acc[j][0] = fma2(xi, wa.x, acc[j][0]);
            acc[j][1] = fma2(xi, wa.y, acc[j][1]);
            acc[j][2] = fma2(xi, wb.x, acc[j][2]);
            acc[j][3] = fma2(xi, wb.y, acc[j][3]);
        }
    }

    #pragma unroll
    for (int j = 0; j < 8; j++) {
        int r = row0 + ((j < 4) ? (ty * 4 + j) : (64 + ty * 4 + (j - 4)));
        if (r < n) {
            uint4 o;
            union { ull u; float2 f; } cv;
            __half2 hh;
            cv.u = acc[j][0]; hh = __floats2half2_rn(cv.f.x, cv.f.y);
            o.x = *reinterpret_cast<unsigned*>(&hh);
            cv.u = acc[j][1]; hh = __floats2half2_rn(cv.f.x, cv.f.y);
            o.y = *reinterpret_cast<unsigned*>(&hh);
            cv.u = acc[j][2]; hh = __floats2half2_rn(cv.f.x, cv.f.y);
            o.z = *reinterpret_cast<unsigned*>(&hh);
            cv.u = acc[j][3]; hh = __floats2half2_rn(cv.f.x, cv.f.y);
            o.w = *reinterpret_cast<unsigned*>(&hh);
            ((uint4*)(C + (size_t)r * D))[tx] = o;
        }
    }
}

// ---------------- GEMM 128->40 with BN prologue (fp16 in/out) ----------------
__global__ void gemm40(const __half* __restrict__ A, const float* __restrict__ W,
                       __half* __restrict__ C, int n,
                       const float* __restrict__ g, const float* __restrict__ be,
                       int statIdx, float fn) {
    __shared__ float sW[128 * 40];
    __shared__ float sX[32 * 132];
    __shared__ float sSc[128], sSh[128];

    int tid = threadIdx.x;
    int row0 = blockIdx.x * 32;

    if (tid < 128) {
        float mean = g_bnsum[statIdx * 128 + tid] / fn;
        float var  = g_bnsumsq[statIdx * 128 + tid] / fn - mean * mean;
        float sc   = g[tid] * rsqrtf(var + 1e-5f);
        sSc[tid] = sc;
        sSh[tid] = be[tid] - mean * sc;
    }
    __syncthreads();

    const float4* W4  = (const float4*)W;
    float4*       sW4 = (float4*)sW;
    #pragma unroll
    for (int i = tid; i < 1280; i += 256) sW4[i] = W4[i];

    const uint2* A2 = (const uint2*)(A + (size_t)row0 * D);
    float4* sX4 = (float4*)sX;
    #pragma unroll
    for (int i = tid; i < 1024; i += 256) {
        int r = i >> 5, c4 = i & 31;
        float4 v = make_float4(0.f, 0.f, 0.f, 0.f);
        if (row0 + r < n) {
            uint2 rv = A2[i];
            float2 f0 = __half22float2(*reinterpret_cast<__half2*>(&rv.x));
            float2 f1 = __half22float2(*reinterpret_cast<__half2*>(&rv.y));
            float4 sc = ((const float4*)sSc)[c4];
            float4 sh = ((const float4*)sSh)[c4];
            v.x = fmaxf(fmaf(f0.x, sc.x, sh.x), 0.f);
            v.y = fmaxf(fmaf(f0.y, sc.y, sh.y), 0.f);
            v.z = fmaxf(fmaf(f1.x, sc.z, sh.z), 0.f);
            v.w = fmaxf(fmaf(f1.y, sc.w, sh.w), 0.f);
        }
        sX4[r * 33 + c4] = v;
    }
    __syncthreads();

    int tx = tid & 7, rt = tid >> 3;
    float acc[5] = {0.f, 0.f, 0.f, 0.f, 0.f};
    #pragma unroll 4
    for (int k = 0; k < 128; k++) {
        float xv = sX[rt * 132 + k];
        #pragma unroll
        for (int j = 0; j < 5; j++)
            acc[j] = fmaf(xv, sW[k * 40 + tx * 5 + j], acc[j]);
    }
    int row = row0 + rt;
    if (row < n) {
        #pragma unroll
        for (int j = 0; j < 5; j++)
            C[(size_t)row * 40 + tx * 5 + j] = __float2half_rn(acc[j]);
    }
}

// ---------------- CSR gather (fp16) + self-loop + bias + BN stats, fp16 h out ----
__global__ void gather128_bn(const __half* __restrict__ xw, const float* __restrict__ b,
                             __half* __restrict__ h, int n, int statIdx) {
    __shared__ float sbs[128], sbss[128];
    int tid = threadIdx.x;
    if (tid < 128) { sbs[tid] = 0.f; sbss[tid] = 0.f; }
    __syncthreads();

    int lane   = tid & 31;
    int warp   = (blockIdx.x * blockDim.x + tid) >> 5;
    int nwarps = (gridDim.x * blockDim.x) >> 5;

    float4 ps  = make_float4(0.f, 0.f, 0.f, 0.f);
    float4 pss = make_float4(0.f, 0.f, 0.f, 0.f);
    float4 bb  = ((const float4*)b)[lane];

    for (int v = warp; v < n; v += nwarps) {
        int beg = g_rowptr[v], end = g_rowptr[v + 1];
        float4 acc = make_float4(0.f, 0.f, 0.f, 0.f);
        for (int i = beg; i < end; i++) {
            int   s = g_esrc[i];
            float w = g_enorm[i];
            uint2 rv = ((const uint2*)(xw + (size_t)s * D))[lane];
            float2 f0 = __half22float2(*reinterpret_cast<__half2*>(&rv.x));
            float2 f1 = __half22float2(*reinterpret_cast<__half2*>(&rv.y));
            acc.x = fmaf(f0.x, w, acc.x);
            acc.y = fmaf(f0.y, w, acc.y);
            acc.z = fmaf(f1.x, w, acc.z);
            acc.w = fmaf(f1.y, w, acc.w);
        }
        float di  = g_dinv[v];
        float di2 = di * di;
        uint2 rv = ((const uint2*)(xw + (size_t)v * D))[lane];
        float2 f0 = __half22float2(*reinterpret_cast<__half2*>(&rv.x));
        float2 f1 = __half22float2(*reinterpret_cast<__half2*>(&rv.y));
        acc.x = fmaf(f0.x, di2, acc.x) + bb.x;
        acc.y = fmaf(f0.y, di2, acc.y) + bb.y;
        acc.z = fmaf(f1.x, di2, acc.z) + bb.z;
        acc.w = fmaf(f1.y, di2, acc.w) + bb.w;

        uint2 o;
        __half2 hh;
        hh = __floats2half2_rn(acc.x, acc.y);
        o.x = *reinterpret_cast<unsigned*>(&hh);
        hh = __floats2half2_rn(acc.z, acc.w);
        o.y = *reinterpret_cast<unsigned*>(&hh);
        ((uint2*)(h + (size_t)v * D))[lane] = o;

        ps.x += acc.x; ps.y += acc.y; ps.z += acc.z; ps.w += acc.w;
        pss.x = fmaf(acc.x, acc.x, pss.x);
        pss.y = fmaf(acc.y, acc.y, pss.y);
        pss.z = fmaf(acc.z, acc.z, pss.z);
        pss.w = fmaf(acc.w, acc.w, pss.w);
    }

    atomicAdd(&sbs[lane * 4 + 0], ps.x);
    atomicAdd(&sbs[lane * 4 + 1], ps.y);
    atomicAdd(&sbs[lane * 4 + 2], ps.z);
    atomicAdd(&sbs[lane * 4 + 3], ps.w);
    atomicAdd(&sbss[lane * 4 + 0], pss.x);
    atomicAdd(&sbss[lane * 4 + 1], pss.y);
    atomicAdd(&sbss[lane * 4 + 2], pss.z);
    atomicAdd(&sbss[lane * 4 + 3], pss.w);
    __syncthreads();
    if (tid < 128) {
        atomicAdd(&g_bnsum[statIdx * 128 + tid],   sbs[tid]);
        atomicAdd(&g_bnsumsq[statIdx * 128 + tid], sbss[tid]);
    }
}

// ---------------- CSR gather (D=40, fp16) + self-loop + bias + log_softmax --------
__global__ void gather40_softmax(const __half* __restrict__ xw2,
                                 const float* __restrict__ b2, float* __restrict__ out,
                                 int n) {
    int lane   = threadIdx.x & 31;
    int warp   = (blockIdx.x * blockDim.x + threadIdx.x) >> 5;
    int nwarps = (gridDim.x * blockDim.x) >> 5;

    for (int v = warp; v < n; v += nwarps) {
        int beg = g_rowptr[v], end = g_rowptr[v + 1];
        float4 acc = make_float4(0.f, 0.f, 0.f, 0.f);
        if (lane < 10) {
            for (int i = beg; i < end; i++) {
                int   s = g_esrc[i];
                float w = g_enorm[i];
                uint2 rv = ((const uint2*)(xw2 + (size_t)s * DOUT))[lane];
                float2 f0 = __half22float2(*reinterpret_cast<__half2*>(&rv.x));
                float2 f1 = __half22float2(*reinterpret_cast<__half2*>(&rv.y));
                acc.x = fmaf(f0.x, w, acc.x);
                acc.y = fmaf(f0.y, w, acc.y);
                acc.z = fmaf(f1.x, w, acc.z);
                acc.w = fmaf(f1.y, w, acc.w);
            }
            float di  = g_dinv[v];
            float di2 = di * di;
            uint2 rv = ((const uint2*)(xw2 + (size_t)v * DOUT))[lane];
            float2 f0 = __half22float2(*reinterpret_cast<__half2*>(&rv.x));
            float2 f1 = __half22float2(*reinterpret_cast<__half2*>(&rv.y));
            float4 bb = ((const float4*)b2)[lane];
            acc.x = fmaf(f0.x, di2, acc.x) + bb.x;
            acc.y = fmaf(f0.y, di2, acc.y) + bb.y;
            acc.z = fmaf(f1.x, di2, acc.z) + bb.z;
            acc.w = fmaf(f1.y, di2, acc.w) + bb.w;
        }
        float m = (lane < 10)
                ? fmaxf(fmaxf(acc.x, acc.y), fmaxf(acc.z, acc.w)) : -1e30f;
        #pragma unroll
        for (int o = 16; o; o >>= 1) m = fmaxf(m, __shfl_xor_sync(0xffffffffu, m, o));
        float s = (lane < 10)
                ? (expf(acc.x - m) + expf(acc.y - m) + expf(acc.z - m) + expf(acc.w - m))
                : 0.f;
        #pragma unroll
        for (int o = 16; o; o >>= 1) s += __shfl_xor_sync(0xffffffffu, s, o);
        float lse = m + logf(s);
        if (lane < 10)
            ((float4*)(out + (size_t)v * DOUT))[lane] =
                make_float4(acc.x - lse, acc.y - lse, acc.z - lse, acc.w - lse);
    }
}

// ---------------- launch ----------------
extern "C" void kernel_launch(void* const* d_in, const int* in_sizes, int n_in,
                              void* d_out, int out_size) {
    const float* x   = (const float*)d_in[0];
    const void*  ei  = d_in[1];
    const float* ew  = (const float*)d_in[2];
    const float* W0  = (const float*)d_in[3];
    const float* b0  = (const float*)d_in[4];
    const float* g0  = (const float*)d_in[5];
    const float* be0 = (const float*)d_in[6];
    const float* W1  = (const float*)d_in[7];
    const float* b1  = (const float*)d_in[8];
    const float* g1  = (const float*)d_in[9];
    const float* be1 = (const float*)d_in[10];
    const float* W2  = (const float*)d_in[11];
    const float* b2  = (const float*)d_in[12];

    int n = in_sizes[0] / D;
    int E = in_sizes[2];
    int twoE = 2 * E;
    float fn = (float)n;

    cudaFuncSetAttribute(gemm128<false>, cudaFuncAttributeMaxDynamicSharedMemorySize, GEMM_SMEM);
    cudaFuncSetAttribute(gemm128<true>,  cudaFuncAttributeMaxDynamicSharedMemorySize, GEMM_SMEM);

    void *p_deg, *p_cnt, *p_fill, *p_bns, *p_bnss, *p_xw, *p_h, *p_xw2;
    cudaGetSymbolAddress(&p_deg,  g_deg);
    cudaGetSymbolAddress(&p_cnt,  g_cnt);
    cudaGetSymbolAddress(&p_fill, g_fill);
    cudaGetSymbolAddress(&p_bns,  g_bnsum);
    cudaGetSymbolAddress(&p_bnss, g_bnsumsq);
    cudaGetSymbolAddress(&p_xw,   g_xw);
    cudaGetSymbolAddress(&p_h,    g_h);
    cudaGetSymbolAddress(&p_xw2,  g_xw2);
    __half* xw  = (__half*)p_xw;
    __half* h   = (__half*)p_h;
    __half* xw2 = (__half*)p_xw2;

    const int T = 256;
    int nb_scan = cdiv(n, 512);
    int gather_blocks = 1184;

    // fork/join: CSR build + stat zeroing (s2) overlapped with layer-0 GEMM (s0).
    cudaStream_t s2;
    cudaEvent_t evF, evJ;
    cudaStreamCreateWithFlags(&s2, cudaStreamNonBlocking);
    cudaEventCreateWithFlags(&evF, cudaEventDisableTiming);
    cudaEventCreateWithFlags(&evJ, cudaEventDisableTiming);

    cudaEventRecord(evF, 0);
    cudaStreamWaitEvent(s2, evF, 0);

    // ---- branch A (s2): zero + convert + CSR build ----
    cudaMemsetAsync(p_deg,  0, (size_t)n * sizeof(float), s2);
    cudaMemsetAsync(p_cnt,  0, (size_t)n * sizeof(int), s2);
    cudaMemsetAsync(p_fill, 0, (size_t)n * sizeof(int), s2);
    cudaMemsetAsync(p_bns,  0, 256 * sizeof(float), s2);
    cudaMemsetAsync(p_bnss, 0, 256 * sizeof(float), s2);
    detect_kernel<<<1, 32, 0, s2>>>((const unsigned*)ei, twoE);
    convert_deg_kernel<<<cdiv(twoE, T), T, 0, s2>>>(ei, ew, E);
    scan1<<<nb_scan, 512, 0, s2>>>(n);
    scan2<<<1, 256, 0, s2>>>(nb_scan);
    scan3<<<cdiv(n, T), T, 0, s2>>>(n, E);
    fill_kernel<<<cdiv(E, T), T, 0, s2>>>(ew, E);
    cudaEventRecord(evJ, s2);

    // ---- branch B (stream 0): layer-0 GEMM ----
    gemm128<false><<<cdiv(n, 128), T, GEMM_SMEM>>>(x, (const __half*)0, W0, xw, n,
                                                   (const float*)0, (const float*)0, 0, fn);

    // join
    cudaStreamWaitEvent(0, evJ, 0);

    // ---- layer 0 aggregate (stats -> buffer 0) ----
    gather128_bn<<<gather_blocks, T>>>(xw, b0, h, n, 0);

    // ---- layer 1 (BN from buffer 0 in prologue) ----
    gemm128<true><<<cdiv(n, 128), T, GEMM_SMEM>>>((const float*)0, h, W1, xw, n,
                                                  g0, be0, 0, fn);
    gather128_bn<<<gather_blocks, T>>>(xw, b1, h, n, 1);

    // ---- layer 2 (BN from buffer 1) + log_softmax ----
    gemm40<<<cdiv(n, 32), T>>>(h, W2, xw2, n, g1, be1, 1, fn);
    gather40_softmax<<<gather_blocks, T>>>(xw2, b2, (float*)d_out, n);

    cudaEventDestroy(evF);
    cudaEventDestroy(evJ);
    cudaStreamDestroy(s2);
}